// round 5
// baseline (speedup 1.0000x reference)
#include <cuda_runtime.h>

// QLSTM: B=512, T=1024, IN=1, H=64.
// 128 blocks x 256 threads, 4 batches/block, persistent over all T.
// Thread (u, bp, gs): u = hidden unit, bp = batch pair {2bp, 2bp+1},
// gs = gate split (gs=0 -> gates i,f ; gs=1 -> gates g,o).
// W_hh rows for this thread's 2 gates live in 64 packed 64-bit registers;
// gate pairs accumulate via fma.rn.f32x2 (FFMA2: 2 MACs/instr).
// h is stored duplicated {h,h} in shared (double-buffered) so one LDS.128
// feeds two FFMA2 multipliers with no pack instructions.
// Gate halves are exchanged between the gs-pair lanes via shfl_xor(1);
// both lanes redundantly (bit-identically) hold c in registers.

#define TPB 256
#define NBATCH 4
#define TSTEPS 1024

typedef unsigned long long u64t;

struct Smem {
  u64t hd[2][NBATCH][64];         // {h,h} packed, double-buffered: 4 KB
  union {
    float wstage[256 * 64];       // W_hh staging: 64 KB
    u64t  xsd[NBATCH][TSTEPS];    // {x,x} packed input: 32 KB
  } un;
};

__device__ __forceinline__ u64t pack2(float lo, float hi) {
  u64t r;
  asm("mov.b64 %0, {%1, %2};" : "=l"(r) : "f"(lo), "f"(hi));
  return r;
}
__device__ __forceinline__ void unpack2(float& lo, float& hi, u64t v) {
  asm("mov.b64 {%0, %1}, %2;" : "=f"(lo), "=f"(hi) : "l"(v));
}
__device__ __forceinline__ u64t ffma2(u64t a, u64t b, u64t c) {
  u64t d;
  asm("fma.rn.f32x2 %0, %1, %2, %3;" : "=l"(d) : "l"(a), "l"(b), "l"(c));
  return d;
}

__device__ __forceinline__ float sigf(float v) {
  return __fdividef(1.0f, 1.0f + __expf(-v));
}
__device__ __forceinline__ float tanhf_fast(float v) {
  return 1.0f - __fdividef(2.0f, __expf(2.0f * v) + 1.0f);
}

extern __shared__ char smem_raw[];

__global__ void __launch_bounds__(TPB, 1) qlstm_kernel(
    const float* __restrict__ x,      // [B, T, 1]
    const float* __restrict__ W_ih,   // [256, 1]
    const float* __restrict__ W_hh,   // [256, 64]
    const float* __restrict__ b_ih,   // [256]
    const float* __restrict__ b_hh,   // [256]
    const float* __restrict__ W_lin,  // [1, 64]
    const float* __restrict__ b_lin,  // [1]
    float* __restrict__ out)          // [B]
{
  Smem& s = *reinterpret_cast<Smem*>(smem_raw);
  const int t  = threadIdx.x;
  const int gs = t & 1;               // gate split: 0 -> {i,f}, 1 -> {g,o}
  const int bp = (t >> 1) & 1;        // batch pair
  const int u  = t >> 2;              // hidden unit 0..63
  const int b0 = 2 * bp;
  const int b1 = b0 + 1;
  const int batch0 = blockIdx.x * NBATCH;

  // ---- stage W_hh into shared (coalesced), then scatter to registers ----
  {
    const float4* src = reinterpret_cast<const float4*>(W_hh);
    float4* dst = reinterpret_cast<float4*>(s.un.wstage);
    for (int i = t; i < 256 * 64 / 4; i += TPB) dst[i] = src[i];
  }
  __syncthreads();

  const int r0 = gs * 128 + u;        // first gate row  (i or g)
  const int r1 = r0 + 64;             // second gate row (f or o)
  u64t Wreg[64];
#pragma unroll
  for (int k = 0; k < 64; k++)
    Wreg[k] = pack2(s.un.wstage[r0 * 64 + k], s.un.wstage[r1 * 64 + k]);
  __syncthreads();                    // done with wstage; union reused for x

  // ---- stage x duplicated {x,x}; zero h buffer 0 ----
  for (int i = t; i < NBATCH * TSTEPS; i += TPB) {
    int bb = i >> 10, tt = i & (TSTEPS - 1);
    float xv = x[(batch0 + bb) * TSTEPS + tt];
    s.un.xsd[bb][tt] = pack2(xv, xv);
  }
  for (int i = t; i < NBATCH * 64; i += TPB)
    (&s.hd[0][0][0])[i] = 0ull;

  const u64t bias2 = pack2(b_ih[r0] + b_hh[r0], b_ih[r1] + b_hh[r1]);
  const u64t wih2  = pack2(W_ih[r0], W_ih[r1]);
  __syncthreads();

  float cA = 0.0f, cB = 0.0f;
  int pb = 0;

  for (int step = 0; step < TSTEPS; step++) {
    u64t a0 = ffma2(wih2, s.un.xsd[b0][step], bias2);
    u64t a1 = ffma2(wih2, s.un.xsd[b1][step], bias2);

    const ulonglong2* __restrict__ h0p =
        reinterpret_cast<const ulonglong2*>(s.hd[pb][b0]);
    const ulonglong2* __restrict__ h1p =
        reinterpret_cast<const ulonglong2*>(s.hd[pb][b1]);
#pragma unroll
    for (int j = 0; j < 32; j++) {
      ulonglong2 H0 = h0p[j];         // {h_2j,h_2j, h_2j+1,h_2j+1} broadcast
      ulonglong2 H1 = h1p[j];
      a0 = ffma2(Wreg[2 * j],     H0.x, a0);
      a1 = ffma2(Wreg[2 * j],     H1.x, a1);
      a0 = ffma2(Wreg[2 * j + 1], H0.y, a0);
      a1 = ffma2(Wreg[2 * j + 1], H1.y, a1);
    }

    // activations on my two gates, both batches
    float p0, q0, p1, q1;
    unpack2(p0, q0, a0);
    unpack2(p1, q1, a1);
    float A0, B0, A1, B1;
    if (gs == 0) {                    // i, f
      A0 = sigf(p0); B0 = sigf(q0);
      A1 = sigf(p1); B1 = sigf(q1);
    } else {                          // g, o
      A0 = tanhf_fast(p0); B0 = sigf(q0);
      A1 = tanhf_fast(p1); B1 = sigf(q1);
    }
    // exchange with gs-partner (adjacent lane)
    float oA0 = __shfl_xor_sync(0xFFFFFFFFu, A0, 1);
    float oB0 = __shfl_xor_sync(0xFFFFFFFFu, B0, 1);
    float oA1 = __shfl_xor_sync(0xFFFFFFFFu, A1, 1);
    float oB1 = __shfl_xor_sync(0xFFFFFFFFu, B1, 1);
    float i0 = gs ? oA0 : A0, f0 = gs ? oB0 : B0;
    float g0 = gs ? A0 : oA0, o0 = gs ? B0 : oB0;
    float i1 = gs ? oA1 : A1, f1 = gs ? oB1 : B1;
    float g1 = gs ? A1 : oA1, o1 = gs ? B1 : oB1;

    cA = fmaf(f0, cA, i0 * g0);
    cB = fmaf(f1, cB, i1 * g1);
    float hn0 = o0 * tanhf_fast(cA);
    float hn1 = o1 * tanhf_fast(cB);

    // write next h buffer: gs=0 covers batch b0, gs=1 covers batch b1
    if (gs == 0) s.hd[pb ^ 1][b0][u] = pack2(hn0, hn0);
    else         s.hd[pb ^ 1][b1][u] = pack2(hn1, hn1);
    pb ^= 1;
    __syncthreads();  // single barrier: double buffer makes it sufficient
  }

  // final linear: out[b] = h_final[b] . W_lin + b_lin
  if (t < NBATCH) {
    float sum = b_lin[0];
#pragma unroll
    for (int k = 0; k < 64; k++) {
      float lo, hi;
      unpack2(lo, hi, s.hd[pb][t][k]);
      sum = fmaf(lo, W_lin[k], sum);
    }
    out[batch0 + t] = sum;
  }
}

extern "C" void kernel_launch(void* const* d_in, const int* in_sizes, int n_in,
                              void* d_out, int out_size) {
  const float* x     = (const float*)d_in[0];
  const float* W_ih  = (const float*)d_in[1];
  const float* W_hh  = (const float*)d_in[2];
  const float* b_ih  = (const float*)d_in[3];
  const float* b_hh  = (const float*)d_in[4];
  const float* W_lin = (const float*)d_in[5];
  const float* b_lin = (const float*)d_in[6];
  float* out = (float*)d_out;

  const int B = out_size;  // 512
  const int nblocks = B / NBATCH;

  cudaFuncSetAttribute(qlstm_kernel,
                       cudaFuncAttributeMaxDynamicSharedMemorySize,
                       (int)sizeof(Smem));
  qlstm_kernel<<<nblocks, TPB, sizeof(Smem)>>>(x, W_ih, W_hh, b_ih, b_hh,
                                               W_lin, b_lin, out);
}